// round 14
// baseline (speedup 1.0000x reference)
#include <cuda_runtime.h>

#define NN 8
#define CC 640
#define HH 48
#define WW 48
#define KK 9
#define WQ 12                 // w-quads per row
#define TYB 16                // output rows per block
#define THREADS (WQ * TYB)    // 192
#define CG 8                  // channels per block (staged together)
#define SROWS (TYB + 2)       // 18 staged rows
#define QS_FLOATS (CG * SROWS * WW)        // 6912
#define FS_FLOATS (TYB * WW * KK)          // 6912
#define SMEM_BYTES ((QS_FLOATS + FS_FLOATS) * 4)   // 55296

__global__ __launch_bounds__(THREADS, 4) void dyn_conv_kernel(
    const float* __restrict__ q,
    const float* __restrict__ df,
    float* __restrict__ out,
    int tail_n4)
{
    extern __shared__ float smem[];
    float* qs  = smem;                 // [CG][SROWS][WW]
    float* fsm = smem + QS_FLOATS;     // [TYB*WW*KK] raw copy of filter block

    // ---- fused tail-zero slice ----
    if (blockIdx.y == CC / CG) {
        const int q_elems = NN * CC * HH * WW;
        float4* p = reinterpret_cast<float4*>(out + q_elems);
        const int tid    = threadIdx.y * WQ + threadIdx.x;
        const int gtid   = (blockIdx.z * gridDim.x + blockIdx.x) * THREADS + tid;
        const int stride = gridDim.x * gridDim.z * THREADS;
        for (int i = gtid; i < tail_n4; i += stride)
            p[i] = make_float4(0.f, 0.f, 0.f, 0.f);
        return;
    }

    const int tx   = threadIdx.x;                 // 0..11
    const int ty   = threadIdx.y;                 // 0..15
    const int tid  = ty * WQ + tx;
    const int lane = tid & 31;
    const int h    = blockIdx.x * TYB + ty;       // this thread's output row
    const int h0m1 = blockIdx.x * TYB - 1;        // global row of staged row 0
    const int c0   = blockIdx.y * CG;
    const int n    = blockIdx.z;
    const int w4   = tx * 4;

    // ---- stage query band: CG channels x 18 rows x 48 w, coalesced ----
    {
        const float4 z4 = make_float4(0.f, 0.f, 0.f, 0.f);
        const float* qbase = q + (size_t)(n * CC + c0) * HH * WW;
#pragma unroll
        for (int it = 0; it < (CG * SROWS * WQ) / THREADS; it++) {   // 9 iters
            int i    = tid + it * THREADS;
            int ch   = i / (SROWS * WQ);
            int rem  = i - ch * (SROWS * WQ);
            int row  = rem / WQ;
            int quad = rem - row * WQ;
            int grow = h0m1 + row;
            float4 v = (grow >= 0 && grow < HH)
                ? *reinterpret_cast<const float4*>(
                      qbase + ((size_t)ch * HH + grow) * WW + quad * 4)
                : z4;
            *reinterpret_cast<float4*>(
                &qs[(ch * SROWS + row) * WW + quad * 4]) = v;
        }
    }

    // ---- stage filter block: 16 rows x 48 w x 9 taps, straight coalesced copy ----
    {
        const float4* src = reinterpret_cast<const float4*>(
            df + (size_t)(n * HH + blockIdx.x * TYB) * WW * KK);
        float4* dst = reinterpret_cast<float4*>(fsm);
#pragma unroll
        for (int it = 0; it < (FS_FLOATS / 4) / THREADS; it++)       // 9 iters
            dst[tid + it * THREADS] = src[tid + it * THREADS];
    }

    __syncthreads();

    // ---- filter for this thread's fixed (h, w4..w4+3) -> registers (from smem) ----
    // fl[j*9+k] = tap k for output (h, w4+j). 9 LDS.128, conflict-free.
    float fl[36];
    {
        const float4* fp = reinterpret_cast<const float4*>(
            fsm + (ty * WW + w4) * KK);
#pragma unroll
        for (int v = 0; v < 9; v++) {
            float4 t = fp[v];
            fl[v * 4 + 0] = t.x;
            fl[v * 4 + 1] = t.y;
            fl[v * 4 + 2] = t.z;
            fl[v * 4 + 3] = t.w;
        }
    }

    const bool lok = (w4 > 0);
    const bool rok = (w4 + 4 < WW);
    const bool lfixlane = (lane == 0)  && lok;    // row-neighbor in other warp
    const bool rfixlane = (lane == 31) && rok;

    float* ob = out + ((size_t)(n * CC + c0) * HH + h) * WW + w4;
    const int CHS = HH * WW;

#pragma unroll
    for (int ch = 0; ch < CG; ch++) {
        const float* qc = &qs[ch * SROWS * WW];
        float4 cur[3];
#pragma unroll
        for (int di = 0; di < 3; di++)
            cur[di] = *reinterpret_cast<const float4*>(
                qc + (ty + di) * WW + w4);

        float e0[3], e1[3];
#pragma unroll
        for (int di = 0; di < 3; di++) {
            float lft = __shfl_up_sync(0xffffffffu, cur[di].w, 1);
            float rgt = __shfl_down_sync(0xffffffffu, cur[di].x, 1);
            if (lfixlane) lft = qc[(ty + di) * WW + w4 - 1];
            if (rfixlane) rgt = qc[(ty + di) * WW + w4 + 4];
            e0[di] = lok ? lft : 0.f;
            e1[di] = rok ? rgt : 0.f;
        }

        float a0 = 0.f, a1 = 0.f, a2 = 0.f, a3 = 0.f;
#pragma unroll
        for (int di = 0; di < 3; di++) {
            float rowv[6];
            rowv[0] = e0[di];
            rowv[1] = cur[di].x; rowv[2] = cur[di].y;
            rowv[3] = cur[di].z; rowv[4] = cur[di].w;
            rowv[5] = e1[di];
#pragma unroll
            for (int dj = 0; dj < 3; dj++) {
                const int k = di * 3 + dj;
                a0 = fmaf(rowv[dj + 0], fl[0 * KK + k], a0);
                a1 = fmaf(rowv[dj + 1], fl[1 * KK + k], a1);
                a2 = fmaf(rowv[dj + 2], fl[2 * KK + k], a2);
                a3 = fmaf(rowv[dj + 3], fl[3 * KK + k], a3);
            }
        }

        float4 o;
        o.x = fmaxf(a0, 0.0f);
        o.y = fmaxf(a1, 0.0f);
        o.z = fmaxf(a2, 0.0f);
        o.w = fmaxf(a3, 0.0f);
        *reinterpret_cast<float4*>(ob + ch * CHS) = o;
    }
}

extern "C" void kernel_launch(void* const* d_in, const int* in_sizes, int n_in,
                              void* d_out, int out_size)
{
    const float* q  = (const float*)d_in[0];
    const float* df = (const float*)d_in[1];
    const int q_elems = NN * CC * HH * WW;
    if (n_in >= 2 && in_sizes[0] != q_elems) {
        const float* t = q; q = df; df = t;
    }

    float* out = (float*)d_out;

    const int tail    = out_size - q_elems;
    const int tail_n4 = (tail > 0) ? tail / 4 : 0;

    static int attr_done = 0;
    if (!attr_done) {
        cudaFuncSetAttribute(dyn_conv_kernel,
                             cudaFuncAttributeMaxDynamicSharedMemorySize,
                             SMEM_BYTES);
        attr_done = 1;
    }

    dim3 blk(WQ, TYB);                                        // 192 threads
    dim3 grd(HH / TYB, CC / CG + (tail_n4 > 0 ? 1 : 0), NN);  // 3 x 81 x 8
    dyn_conv_kernel<<<grd, blk, SMEM_BYTES>>>(q, df, out, tail_n4);
}

// round 15
// speedup vs baseline: 1.0600x; 1.0600x over previous
#include <cuda_runtime.h>

#define NN 8
#define CC 640
#define HH 48
#define WW 48
#define KK 9
#define WQ 12                  // w-quads per row
#define TYB 16                 // output rows per block
#define THREADS (WQ * TYB)     // 192
#define CG 8                   // channels staged per round
#define NR 4                   // rounds per block
#define CGT (CG * NR)          // 32 channels per block
#define SROWS (TYB + 2)        // 18 staged rows

__global__ __launch_bounds__(THREADS, 4) void dyn_conv_kernel(
    const float* __restrict__ q,
    const float* __restrict__ df,
    float* __restrict__ out,
    int tail_n4)
{
    __shared__ float qs[CG][SROWS][WW];   // 27648 B, reused across NR rounds

    // ---- fused tail-zero slice ----
    if (blockIdx.y == CC / CGT) {
        const int q_elems = NN * CC * HH * WW;
        float4* p = reinterpret_cast<float4*>(out + q_elems);
        const int tid    = threadIdx.y * WQ + threadIdx.x;
        const int gtid   = (blockIdx.z * gridDim.x + blockIdx.x) * THREADS + tid;
        const int stride = gridDim.x * gridDim.z * THREADS;
        for (int i = gtid; i < tail_n4; i += stride)
            p[i] = make_float4(0.f, 0.f, 0.f, 0.f);
        return;
    }

    const int tx   = threadIdx.x;                 // 0..11
    const int ty   = threadIdx.y;                 // 0..15
    const int tid  = ty * WQ + tx;
    const int lane = tid & 31;
    const int h    = blockIdx.x * TYB + ty;       // this thread's output row
    const int h0m1 = blockIdx.x * TYB - 1;        // global row of staged row 0
    const int cb0  = blockIdx.y * CGT;            // first channel of this block
    const int n    = blockIdx.z;
    const int w4   = tx * 4;

    // ---- filter for this thread's fixed (h, w4..w4+3), in registers.
    // Loaded ONCE, reused for all CGT=32 channels (128 outputs).
    float fl[36];
    {
        const float4* fp = reinterpret_cast<const float4*>(
            df + ((size_t)(n * HH + h) * WW + (size_t)w4) * KK);
#pragma unroll
        for (int v = 0; v < 9; v++) {
            float4 t = fp[v];
            fl[v * 4 + 0] = t.x;
            fl[v * 4 + 1] = t.y;
            fl[v * 4 + 2] = t.z;
            fl[v * 4 + 3] = t.w;
        }
    }

    const bool lok = (w4 > 0);
    const bool rok = (w4 + 4 < WW);
    const bool lfixlane = (lane == 0)  && lok;    // row-neighbor in other warp
    const bool rfixlane = (lane == 31) && rok;

    const float4 z4 = make_float4(0.f, 0.f, 0.f, 0.f);
    const int CHS = HH * WW;

    for (int r = 0; r < NR; r++) {
        const int c0 = cb0 + r * CG;

        // ---- stage query band: CG channels x 18 rows x 48 w, coalesced ----
        {
            const float* qbase = q + (size_t)(n * CC + c0) * HH * WW;
#pragma unroll
            for (int it = 0; it < (CG * SROWS * WQ) / THREADS; it++) { // 9 iters
                int i    = tid + it * THREADS;
                int ch   = i / (SROWS * WQ);
                int rem  = i - ch * (SROWS * WQ);
                int row  = rem / WQ;
                int quad = rem - row * WQ;
                int grow = h0m1 + row;
                float4 v = (grow >= 0 && grow < HH)
                    ? *reinterpret_cast<const float4*>(
                          qbase + ((size_t)ch * HH + grow) * WW + quad * 4)
                    : z4;
                *reinterpret_cast<float4*>(&qs[ch][row][quad * 4]) = v;
            }
        }
        __syncthreads();

        float* ob = out + ((size_t)(n * CC + c0) * HH + h) * WW + w4;

#pragma unroll
        for (int ch = 0; ch < CG; ch++) {
            float4 cur[3];
#pragma unroll
            for (int di = 0; di < 3; di++)
                cur[di] = *reinterpret_cast<const float4*>(&qs[ch][ty + di][w4]);

            float e0[3], e1[3];
#pragma unroll
            for (int di = 0; di < 3; di++) {
                float lft = __shfl_up_sync(0xffffffffu, cur[di].w, 1);
                float rgt = __shfl_down_sync(0xffffffffu, cur[di].x, 1);
                if (lfixlane) lft = qs[ch][ty + di][w4 - 1];
                if (rfixlane) rgt = qs[ch][ty + di][w4 + 4];
                e0[di] = lok ? lft : 0.f;
                e1[di] = rok ? rgt : 0.f;
            }

            float a0 = 0.f, a1 = 0.f, a2 = 0.f, a3 = 0.f;
#pragma unroll
            for (int di = 0; di < 3; di++) {
                float rowv[6];
                rowv[0] = e0[di];
                rowv[1] = cur[di].x; rowv[2] = cur[di].y;
                rowv[3] = cur[di].z; rowv[4] = cur[di].w;
                rowv[5] = e1[di];
#pragma unroll
                for (int dj = 0; dj < 3; dj++) {
                    const int k = di * 3 + dj;
                    a0 = fmaf(rowv[dj + 0], fl[0 * KK + k], a0);
                    a1 = fmaf(rowv[dj + 1], fl[1 * KK + k], a1);
                    a2 = fmaf(rowv[dj + 2], fl[2 * KK + k], a2);
                    a3 = fmaf(rowv[dj + 3], fl[3 * KK + k], a3);
                }
            }

            float4 o;
            o.x = fmaxf(a0, 0.0f);
            o.y = fmaxf(a1, 0.0f);
            o.z = fmaxf(a2, 0.0f);
            o.w = fmaxf(a3, 0.0f);
            *reinterpret_cast<float4*>(ob + ch * CHS) = o;
        }

        if (r + 1 < NR) __syncthreads();   // WAR: compute done before re-stage
    }
}

extern "C" void kernel_launch(void* const* d_in, const int* in_sizes, int n_in,
                              void* d_out, int out_size)
{
    const float* q  = (const float*)d_in[0];
    const float* df = (const float*)d_in[1];
    const int q_elems = NN * CC * HH * WW;
    if (n_in >= 2 && in_sizes[0] != q_elems) {
        const float* t = q; q = df; df = t;
    }

    float* out = (float*)d_out;

    const int tail    = out_size - q_elems;
    const int tail_n4 = (tail > 0) ? tail / 4 : 0;

    dim3 blk(WQ, TYB);                                         // 192 threads
    dim3 grd(HH / TYB, CC / CGT + (tail_n4 > 0 ? 1 : 0), NN);  // 3 x 21 x 8
    dyn_conv_kernel<<<grd, blk>>>(q, df, out, tail_n4);
}

// round 16
// speedup vs baseline: 1.2320x; 1.1623x over previous
#include <cuda_runtime.h>

#define NN 8
#define CC 640
#define HH 48
#define WW 48
#define KK 9
#define WQ 12                  // w-quads per row
#define TYB 16                 // output rows per block
#define THREADS (WQ * TYB)     // 192
#define CG 4                   // channels staged per round
#define NR 4                   // rounds per block
#define CGT (CG * NR)          // 16 channels per block
#define SROWS (TYB + 2)        // 18 staged rows
#define STAGE_V4 (CG * SROWS * WQ)   // 864 float4s per round

__global__ __launch_bounds__(THREADS, 4) void dyn_conv_kernel(
    const float* __restrict__ q,
    const float* __restrict__ df,
    float* __restrict__ out,
    int tail_n4)
{
    __shared__ float qs[2][CG][SROWS][WW];   // 2 x 13824 B = 27648 B

    // ---- fused tail-zero slice ----
    if (blockIdx.y == CC / CGT) {
        const int q_elems = NN * CC * HH * WW;
        float4* p = reinterpret_cast<float4*>(out + q_elems);
        const int tid    = threadIdx.y * WQ + threadIdx.x;
        const int gtid   = (blockIdx.z * gridDim.x + blockIdx.x) * THREADS + tid;
        const int stride = gridDim.x * gridDim.z * THREADS;
        for (int i = gtid; i < tail_n4; i += stride)
            p[i] = make_float4(0.f, 0.f, 0.f, 0.f);
        return;
    }

    const int tx   = threadIdx.x;                 // 0..11
    const int ty   = threadIdx.y;                 // 0..15
    const int tid  = ty * WQ + tx;
    const int lane = tid & 31;
    const int h    = blockIdx.x * TYB + ty;       // this thread's output row
    const int h0m1 = blockIdx.x * TYB - 1;        // global row of staged row 0
    const int cb0  = blockIdx.y * CGT;            // first channel of this block
    const int n    = blockIdx.z;
    const int w4   = tx * 4;

    // stage one round's band via cp.async (zero-fill OOB rows with srcsz=0)
    auto stage = [&](int r, int buf) {
        const float* qbase = q + (size_t)(n * CC + cb0 + r * CG) * HH * WW;
#pragma unroll
        for (int it = 0; it < (STAGE_V4 + THREADS - 1) / THREADS; it++) { // 5
            int i = tid + it * THREADS;
            if (i < STAGE_V4) {
                int ch   = i / (SROWS * WQ);
                int rem  = i - ch * (SROWS * WQ);
                int row  = rem / WQ;
                int quad = rem - row * WQ;
                int grow = h0m1 + row;
                const float* src =
                    qbase + ((size_t)ch * HH + grow) * WW + quad * 4;
                unsigned dst = (unsigned)__cvta_generic_to_shared(
                    &qs[buf][ch][row][quad * 4]);
                int srcsz = (grow >= 0 && grow < HH) ? 16 : 0;
                asm volatile("cp.async.cg.shared.global [%0], [%1], 16, %2;"
                             :: "r"(dst), "l"(src), "r"(srcsz));
            }
        }
        asm volatile("cp.async.commit_group;");
    };

    stage(0, 0);

    // ---- filter for this thread's fixed (h, w4..w4+3), in registers;
    // overlaps with the first in-flight cp.async group ----
    float fl[36];
    {
        const float4* fp = reinterpret_cast<const float4*>(
            df + ((size_t)(n * HH + h) * WW + (size_t)w4) * KK);
#pragma unroll
        for (int v = 0; v < 9; v++) {
            float4 t = fp[v];
            fl[v * 4 + 0] = t.x;
            fl[v * 4 + 1] = t.y;
            fl[v * 4 + 2] = t.z;
            fl[v * 4 + 3] = t.w;
        }
    }

    const bool lok = (w4 > 0);
    const bool rok = (w4 + 4 < WW);
    const bool lfixlane = (lane == 0)  && lok;    // row-neighbor in other warp
    const bool rfixlane = (lane == 31) && rok;

    const int CHS = HH * WW;

#pragma unroll
    for (int r = 0; r < NR; r++) {
        const int buf = r & 1;

        if (r + 1 < NR) {
            stage(r + 1, buf ^ 1);
            asm volatile("cp.async.wait_group 1;");   // round r's group done
        } else {
            asm volatile("cp.async.wait_group 0;");
        }
        __syncthreads();

        float* ob = out + ((size_t)(n * CC + cb0 + r * CG) * HH + h) * WW + w4;

#pragma unroll
        for (int ch = 0; ch < CG; ch++) {
            float4 cur[3];
#pragma unroll
            for (int di = 0; di < 3; di++)
                cur[di] = *reinterpret_cast<const float4*>(
                    &qs[buf][ch][ty + di][w4]);

            float e0[3], e1[3];
#pragma unroll
            for (int di = 0; di < 3; di++) {
                float lft = __shfl_up_sync(0xffffffffu, cur[di].w, 1);
                float rgt = __shfl_down_sync(0xffffffffu, cur[di].x, 1);
                if (lfixlane) lft = qs[buf][ch][ty + di][w4 - 1];
                if (rfixlane) rgt = qs[buf][ch][ty + di][w4 + 4];
                e0[di] = lok ? lft : 0.f;
                e1[di] = rok ? rgt : 0.f;
            }

            float a0 = 0.f, a1 = 0.f, a2 = 0.f, a3 = 0.f;
#pragma unroll
            for (int di = 0; di < 3; di++) {
                float rowv[6];
                rowv[0] = e0[di];
                rowv[1] = cur[di].x; rowv[2] = cur[di].y;
                rowv[3] = cur[di].z; rowv[4] = cur[di].w;
                rowv[5] = e1[di];
#pragma unroll
                for (int dj = 0; dj < 3; dj++) {
                    const int k = di * 3 + dj;
                    a0 = fmaf(rowv[dj + 0], fl[0 * KK + k], a0);
                    a1 = fmaf(rowv[dj + 1], fl[1 * KK + k], a1);
                    a2 = fmaf(rowv[dj + 2], fl[2 * KK + k], a2);
                    a3 = fmaf(rowv[dj + 3], fl[3 * KK + k], a3);
                }
            }

            float4 o;
            o.x = fmaxf(a0, 0.0f);
            o.y = fmaxf(a1, 0.0f);
            o.z = fmaxf(a2, 0.0f);
            o.w = fmaxf(a3, 0.0f);
            *reinterpret_cast<float4*>(ob + ch * CHS) = o;
        }

        if (r + 2 < NR) __syncthreads();   // WAR: buf reused by stage(r+2)
    }
}

extern "C" void kernel_launch(void* const* d_in, const int* in_sizes, int n_in,
                              void* d_out, int out_size)
{
    const float* q  = (const float*)d_in[0];
    const float* df = (const float*)d_in[1];
    const int q_elems = NN * CC * HH * WW;
    if (n_in >= 2 && in_sizes[0] != q_elems) {
        const float* t = q; q = df; df = t;
    }

    float* out = (float*)d_out;

    const int tail    = out_size - q_elems;
    const int tail_n4 = (tail > 0) ? tail / 4 : 0;

    dim3 blk(WQ, TYB);                                         // 192 threads
    dim3 grd(HH / TYB, CC / CGT + (tail_n4 > 0 ? 1 : 0), NN);  // 3 x 41 x 8
    dyn_conv_kernel<<<grd, blk>>>(q, df, out, tail_n4);
}